// round 2
// baseline (speedup 1.0000x reference)
#include <cuda_runtime.h>

// out[b] = dot(user_factors[users[b]], item_factors[items[b]]), D = 64, fp32.
//
// Latency-bound gather workload: one warp handles 4 batch elements.
//  - 8 index loads (2 cache lines) issued back-to-back (MLP for the idx stage)
//  - 8 independent 256B row loads (LDG.64 per lane, MLP=8 per warp)
//  - 4 interleaved warp butterfly reductions (hides SHFL latency)
// 512 blocks x 256 threads -> single wave on 148 SMs, no wave transition.

#define D 64
#define ELEMS_PER_WARP 4
#define WARPS_PER_BLOCK 8
#define THREADS (WARPS_PER_BLOCK * 32)

__global__ __launch_bounds__(THREADS)
void mf_dot_kernel(const int* __restrict__ users,
                   const int* __restrict__ items,
                   const float* __restrict__ user_factors,
                   const float* __restrict__ item_factors,
                   float* __restrict__ out,
                   int batch)
{
    int warp_id = (blockIdx.x * WARPS_PER_BLOCK) + (threadIdx.x >> 5);
    int lane = threadIdx.x & 31;
    int base = warp_id * ELEMS_PER_WARP;
    if (base >= batch) return;

    // Stage 1: front-batch all index loads (same 16B region -> 1-2 sectors).
    int uidx[ELEMS_PER_WARP], iidx[ELEMS_PER_WARP];
    #pragma unroll
    for (int e = 0; e < ELEMS_PER_WARP; e++) {
        uidx[e] = __ldg(&users[base + e]);
        iidx[e] = __ldg(&items[base + e]);
    }

    // Stage 2: 8 independent coalesced row loads (256B each), MLP=8.
    float2 u[ELEMS_PER_WARP], v[ELEMS_PER_WARP];
    #pragma unroll
    for (int e = 0; e < ELEMS_PER_WARP; e++) {
        const float2* u_row = reinterpret_cast<const float2*>(
            user_factors + (long long)uidx[e] * D);
        const float2* v_row = reinterpret_cast<const float2*>(
            item_factors + (long long)iidx[e] * D);
        u[e] = __ldg(&u_row[lane]);
        v[e] = __ldg(&v_row[lane]);
    }

    // Stage 3: per-element partial dot, then 4 interleaved butterfly reductions.
    float acc[ELEMS_PER_WARP];
    #pragma unroll
    for (int e = 0; e < ELEMS_PER_WARP; e++)
        acc[e] = fmaf(u[e].x, v[e].x, u[e].y * v[e].y);

    #pragma unroll
    for (int off = 16; off > 0; off >>= 1) {
        #pragma unroll
        for (int e = 0; e < ELEMS_PER_WARP; e++)
            acc[e] += __shfl_xor_sync(0xFFFFFFFFu, acc[e], off);
    }

    if (lane < ELEMS_PER_WARP) {
        // Move result for element `lane` into this lane via one more shuffle-free
        // trick: lane 0 holds all reduced values (butterfly leaves full warp
        // with the sum, so every lane has every acc[e]). Coalesced 4-wide store.
        out[base + lane] =
            (lane == 0) ? acc[0] : (lane == 1) ? acc[1] : (lane == 2) ? acc[2] : acc[3];
    }
}

extern "C" void kernel_launch(void* const* d_in, const int* in_sizes, int n_in,
                              void* d_out, int out_size)
{
    const int*   users        = (const int*)  d_in[0];
    const int*   items        = (const int*)  d_in[1];
    const float* user_factors = (const float*)d_in[2];
    const float* item_factors = (const float*)d_in[3];
    float*       out          = (float*)      d_out;

    int batch = in_sizes[0];
    int warps = (batch + ELEMS_PER_WARP - 1) / ELEMS_PER_WARP;
    int blocks = (warps + WARPS_PER_BLOCK - 1) / WARPS_PER_BLOCK;
    mf_dot_kernel<<<blocks, THREADS>>>(users, items, user_factors, item_factors, out, batch);
}